// round 12
// baseline (speedup 1.0000x reference)
#include <cuda_runtime.h>
#include <math.h>

// StandardTRM fused fp32 kernel, v2.
// Tile = 64 rows, 512 threads (16 warps, 4/SMSP), thread microtile = 4x8.
// Warp w owns rows 4w..4w+3 entirely -> LayerNorm is a pure warp-shuffle reduce.
// z,y,h tiles live in SMEM for the whole 18-layer + 3-combine chain.
// Weights streamed from L2 via double-buffered cp.async slabs (8 rows x 256 cols).
// Inner product uses packed fma.rn.f32x2; W operands loaded as ulonglong2 so the
// LDS.128 result pairs feed fma.f32x2 directly (no repack movs).

#define MT   64          // rows per CTA tile
#define LDA  256         // row stride (floats) for SMEM tiles
#define KS   8           // K rows per weight slab
#define NT   512         // threads per CTA
#define LN_EPS_F 1e-5f

typedef unsigned long long u64;

__device__ __forceinline__ u64 pk2(float x, float y){
  u64 r; asm("mov.b64 %0, {%1, %2};" : "=l"(r) : "f"(x), "f"(y)); return r;
}
__device__ __forceinline__ void upk2(u64 v, float& x, float& y){
  asm("mov.b64 {%0, %1}, %2;" : "=f"(x), "=f"(y) : "l"(v));
}
__device__ __forceinline__ void fma2(u64& c, u64 a, u64 b){
  asm("fma.rn.f32x2 %0, %1, %2, %0;" : "+l"(c) : "l"(a), "l"(b));
}
__device__ __forceinline__ void cp16(float* s, const float* g){
  unsigned a = (unsigned)__cvta_generic_to_shared(s);
  asm volatile("cp.async.cg.shared.global [%0], [%1], 16;" :: "r"(a), "l"(g));
}
__device__ __forceinline__ void cpcommit(){ asm volatile("cp.async.commit_group;" ::: "memory"); }
__device__ __forceinline__ void cpwait0(){ asm volatile("cp.async.wait_group 0;" ::: "memory"); }

__device__ __forceinline__ float gelu_exact(float v){
  return 0.5f * v * (1.0f + erff(v * 0.7071067811865475f));
}

#define UNPACK8(ACC, I, C) do {                         \
    upk2((ACC)[(I)*4+0], (C)[0], (C)[1]);               \
    upk2((ACC)[(I)*4+1], (C)[2], (C)[3]);               \
    upk2((ACC)[(I)*4+2], (C)[4], (C)[5]);               \
    upk2((ACC)[(I)*4+3], (C)[6], (C)[7]);               \
  } while(0)

// acc[64,256] (+)= sA[64, K=256] @ W[256 x 256cols], W row stride = ldw floats.
// acc: 16 u64 per thread: acc[i*4+j] = cols (tx*8+2j, +1), row ty*4+i.
__device__ __forceinline__ void mm256(u64* __restrict__ acc,
                                      const float* __restrict__ sA,
                                      const float* __restrict__ gW, int ldw,
                                      float* __restrict__ sW,
                                      int tid, int ty, int tx)
{
  const int e  = tid * 4;      // this thread's 4-float chunk within an 8x256 slab
  const int er = e >> 8;
  const int ec = e & 255;
  // prefetch slab 0 into buffer 0
  cp16(sW + e, gW + er * ldw + ec);
  cpcommit();

  const float* Abase = sA + ty * 4 * LDA;
  const int wcol = tx * 8;

  for (int s = 0; s < 32; ++s){
    cpwait0();
    __syncthreads();
    if (s < 31){
      float* dst = sW + ((s + 1) & 1) * (KS * 256);
      cp16(dst + e, gW + (s + 1) * KS * ldw + er * ldw + ec);
      cpcommit();
    }
    const float* w = sW + (s & 1) * (KS * 256) + wcol;
    const float* A = Abase + s * KS;
#pragma unroll
    for (int k4 = 0; k4 < KS; k4 += 4){
      float4 av[4];
#pragma unroll
      for (int i = 0; i < 4; ++i)
        av[i] = *(const float4*)(A + i * LDA + k4);    // warp-uniform broadcast
#pragma unroll
      for (int t = 0; t < 4; ++t){
        const float* wr = w + (k4 + t) * 256;
        ulonglong2 wp0 = *(const ulonglong2*)(wr);     // cols n0..n0+3 as 2 f32x2
        ulonglong2 wp1 = *(const ulonglong2*)(wr + 4); // cols n0+4..n0+7
#pragma unroll
        for (int i = 0; i < 4; ++i){
          float a = (t == 0) ? av[i].x : (t == 1) ? av[i].y : (t == 2) ? av[i].z : av[i].w;
          u64 a2 = pk2(a, a);
          fma2(acc[i*4+0], a2, wp0.x);
          fma2(acc[i*4+1], a2, wp0.y);
          fma2(acc[i*4+2], a2, wp1.x);
          fma2(acc[i*4+3], a2, wp1.y);
        }
      }
    }
  }
}

__global__ void __launch_bounds__(NT, 1)
trm_fused_kernel(const float* __restrict__ x,
                 const float* __restrict__ W_in,   const float* __restrict__ b_in,
                 const float* __restrict__ y_init,
                 const float* __restrict__ W_up,   const float* __restrict__ b_up,
                 const float* __restrict__ W_down, const float* __restrict__ b_down,
                 const float* __restrict__ ln_w,   const float* __restrict__ ln_b,
                 const float* __restrict__ W_comb, const float* __restrict__ b_comb,
                 const float* __restrict__ W_yt,   const float* __restrict__ b_yt,
                 const float* __restrict__ W_head, const float* __restrict__ b_head,
                 float* __restrict__ out)
{
  extern __shared__ float sm[];
  float* sZ = sm;                 // [64][256]
  float* sY = sZ + MT * LDA;      // [64][256]
  float* sH = sY + MT * LDA;      // [64][256]
  float* sW = sH + MT * LDA;      // 2 slabs of [8][256]

  const int tid = threadIdx.x;
  const int tx  = tid & 31;
  const int ty  = tid >> 5;       // warp id 0..15, owns rows 4*ty..4*ty+3
  const int n0  = tx * 8;
  const int r0  = blockIdx.x * MT;

  // ---- load x tile into sZ ----
  for (int e = tid * 4; e < MT * 256; e += NT * 4){
    int r = e >> 8, c = e & 255;
    *(float4*)(sZ + r * LDA + c) = *(const float4*)(x + (size_t)(r0 + r) * 256 + c);
  }
  __syncthreads();

  // ---- z = x @ W_in + b_in ; y = y_init ----
  {
    u64 acc[16];
#pragma unroll
    for (int i = 0; i < 16; ++i) acc[i] = 0ull;
    mm256(acc, sZ, W_in, 256, sW, tid, ty, tx);
    __syncthreads();                    // all reads of sZ (x data) done before overwrite
    float bi[8], yv[8];
#pragma unroll
    for (int j = 0; j < 8; ++j){ bi[j] = b_in[n0 + j]; yv[j] = y_init[n0 + j]; }
#pragma unroll
    for (int i = 0; i < 4; ++i){
      float C[8]; UNPACK8(acc, i, C);
      float* zr = sZ + (ty * 4 + i) * LDA + n0;
      float* yr = sY + (ty * 4 + i) * LDA + n0;
#pragma unroll
      for (int j = 0; j < 8; ++j){ zr[j] = C[j] + bi[j]; yr[j] = yv[j]; }
    }
    __syncthreads();
  }

  // ---- 3 H-cycles ----
  for (int hc = 0; hc < 3; ++hc){
    // ---- 6 L-cycles ----
    for (int lc = 0; lc < 6; ++lc){
      u64 accD[16];
#pragma unroll
      for (int i = 0; i < 16; ++i) accD[i] = 0ull;

      // h = gelu(z @ W_up + b_up) in 4 chunks of 256 cols; accD += h_chunk @ W_down_chunk
      for (int c = 0; c < 4; ++c){
        u64 accU[16];
#pragma unroll
        for (int i = 0; i < 16; ++i) accU[i] = 0ull;
        mm256(accU, sZ, W_up + c * 256, 1024, sW, tid, ty, tx);
        float bu[8];
#pragma unroll
        for (int j = 0; j < 8; ++j) bu[j] = b_up[c * 256 + n0 + j];
#pragma unroll
        for (int i = 0; i < 4; ++i){
          float C[8]; UNPACK8(accU, i, C);
          float* hr = sH + (ty * 4 + i) * LDA + n0;
#pragma unroll
          for (int j = 0; j < 8; ++j) hr[j] = gelu_exact(C[j] + bu[j]);
        }
        // down-proj chunk: first internal __syncthreads of mm256 orders the sH writes
        mm256(accD, sH, W_down + c * 256 * 256, 256, sW, tid, ty, tx);
      }

      // ---- residual + LayerNorm, write back to sZ ----
      __syncthreads();
      float bd[8], lw[8], lb[8];
#pragma unroll
      for (int j = 0; j < 8; ++j){
        bd[j] = b_down[n0 + j]; lw[j] = ln_w[n0 + j]; lb[j] = ln_b[n0 + j];
      }
      float T[4][8], ps[4], pq[4];
#pragma unroll
      for (int i = 0; i < 4; ++i){
        float C[8]; UNPACK8(accD, i, C);
        const float* zr = sZ + (ty * 4 + i) * LDA + n0;
        float s = 0.f, q = 0.f;
#pragma unroll
        for (int j = 0; j < 8; ++j){
          float v = zr[j] + C[j] + bd[j];
          T[i][j] = v; s += v; q += v * v;
        }
        ps[i] = s; pq[i] = q;
      }
#pragma unroll
      for (int off = 16; off > 0; off >>= 1){
#pragma unroll
        for (int i = 0; i < 4; ++i){
          ps[i] += __shfl_xor_sync(0xffffffffu, ps[i], off);
          pq[i] += __shfl_xor_sync(0xffffffffu, pq[i], off);
        }
      }
#pragma unroll
      for (int i = 0; i < 4; ++i){
        float mu  = ps[i] * (1.0f / 256.0f);
        float var = pq[i] * (1.0f / 256.0f) - mu * mu;
        float rs  = rsqrtf(var + LN_EPS_F);
        float* zr = sZ + (ty * 4 + i) * LDA + n0;
#pragma unroll
        for (int j = 0; j < 8; ++j)
          zr[j] = (T[i][j] - mu) * rs * lw[j] + lb[j];
      }
      __syncthreads();
    }

    // ---- combine: h = gelu([z|y] @ W_comb + b_comb); y += h @ W_yt + b_yt ----
    {
      u64 acc[16];
#pragma unroll
      for (int i = 0; i < 16; ++i) acc[i] = 0ull;
      mm256(acc, sZ, W_comb,             256, sW, tid, ty, tx);
      mm256(acc, sY, W_comb + 256 * 256, 256, sW, tid, ty, tx);
      float bc[8];
#pragma unroll
      for (int j = 0; j < 8; ++j) bc[j] = b_comb[n0 + j];
#pragma unroll
      for (int i = 0; i < 4; ++i){
        float C[8]; UNPACK8(acc, i, C);
        float* hr = sH + (ty * 4 + i) * LDA + n0;
#pragma unroll
        for (int j = 0; j < 8; ++j) hr[j] = gelu_exact(C[j] + bc[j]);
      }
      u64 acc2[16];
#pragma unroll
      for (int i = 0; i < 16; ++i) acc2[i] = 0ull;
      mm256(acc2, sH, W_yt, 256, sW, tid, ty, tx);
      __syncthreads();
      float by[8];
#pragma unroll
      for (int j = 0; j < 8; ++j) by[j] = b_yt[n0 + j];
#pragma unroll
      for (int i = 0; i < 4; ++i){
        float C[8]; UNPACK8(acc2, i, C);
        float* yr = sY + (ty * 4 + i) * LDA + n0;
#pragma unroll
        for (int j = 0; j < 8; ++j) yr[j] += C[j] + by[j];
      }
      __syncthreads();
    }
  }

  // ---- head: out = y @ W_head + b_head  (N=10) ----
  __syncthreads();
  for (int e = tid; e < MT * 10; e += NT){
    int m = e / 10;
    int n = e - m * 10;
    float s = b_head[n];
    const float* yr = sY + m * LDA;
    for (int k = 0; k < 256; ++k)
      s += yr[k] * W_head[k * 10 + n];
    out[(size_t)(r0 + m) * 10 + n] = s;
  }
}

extern "C" void kernel_launch(void* const* d_in, const int* in_sizes, int n_in,
                              void* d_out, int out_size)
{
  const float* x      = (const float*)d_in[0];
  const float* W_in   = (const float*)d_in[1];
  const float* b_in   = (const float*)d_in[2];
  const float* y_init = (const float*)d_in[3];
  const float* W_up   = (const float*)d_in[4];
  const float* b_up   = (const float*)d_in[5];
  const float* W_down = (const float*)d_in[6];
  const float* b_down = (const float*)d_in[7];
  const float* ln_w   = (const float*)d_in[8];
  const float* ln_b   = (const float*)d_in[9];
  const float* W_comb = (const float*)d_in[10];
  const float* b_comb = (const float*)d_in[11];
  const float* W_yt   = (const float*)d_in[12];
  const float* b_yt   = (const float*)d_in[13];
  const float* W_head = (const float*)d_in[14];
  const float* b_head = (const float*)d_in[15];
  float* out = (float*)d_out;

  const int B = in_sizes[0] / 256;           // rows
  const size_t smem = (size_t)(3 * MT * LDA + 2 * KS * 256) * sizeof(float); // 212992 B

  cudaFuncSetAttribute(trm_fused_kernel,
                       cudaFuncAttributeMaxDynamicSharedMemorySize, (int)smem);

  trm_fused_kernel<<<B / MT, NT, smem>>>(
      x, W_in, b_in, y_init, W_up, b_up, W_down, b_down,
      ln_w, ln_b, W_comb, b_comb, W_yt, b_yt, W_head, b_head, out);
}

// round 13
// speedup vs baseline: 1.0573x; 1.0573x over previous
#include <cuda_runtime.h>
#include <math.h>

// StandardTRM fused fp32 kernel, v2.
// Tile = 64 rows, 512 threads (16 warps, 4/SMSP), thread microtile = 4x8.
// Warp w owns rows 4w..4w+3 entirely -> LayerNorm is a pure warp-shuffle reduce.
// z,y,h tiles live in SMEM for the whole 18-layer + 3-combine chain.
// Weights streamed from L2 via double-buffered cp.async slabs (8 rows x 256 cols).
// Inner product uses packed fma.rn.f32x2; W operands loaded as ulonglong2 so the
// LDS.128 result pairs feed fma.f32x2 directly (no repack movs).

#define MT   64          // rows per CTA tile
#define LDA  256         // row stride (floats) for SMEM tiles
#define KS   8           // K rows per weight slab
#define NT   512         // threads per CTA
#define LN_EPS_F 1e-5f

typedef unsigned long long u64;

__device__ __forceinline__ u64 pk2(float x, float y){
  u64 r; asm("mov.b64 %0, {%1, %2};" : "=l"(r) : "f"(x), "f"(y)); return r;
}
__device__ __forceinline__ void upk2(u64 v, float& x, float& y){
  asm("mov.b64 {%0, %1}, %2;" : "=f"(x), "=f"(y) : "l"(v));
}
__device__ __forceinline__ void fma2(u64& c, u64 a, u64 b){
  asm("fma.rn.f32x2 %0, %1, %2, %0;" : "+l"(c) : "l"(a), "l"(b));
}
__device__ __forceinline__ void cp16(float* s, const float* g){
  unsigned a = (unsigned)__cvta_generic_to_shared(s);
  asm volatile("cp.async.cg.shared.global [%0], [%1], 16;" :: "r"(a), "l"(g));
}
__device__ __forceinline__ void cpcommit(){ asm volatile("cp.async.commit_group;" ::: "memory"); }
__device__ __forceinline__ void cpwait0(){ asm volatile("cp.async.wait_group 0;" ::: "memory"); }

__device__ __forceinline__ float gelu_exact(float v){
  return 0.5f * v * (1.0f + erff(v * 0.7071067811865475f));
}

#define UNPACK8(ACC, I, C) do {                         \
    upk2((ACC)[(I)*4+0], (C)[0], (C)[1]);               \
    upk2((ACC)[(I)*4+1], (C)[2], (C)[3]);               \
    upk2((ACC)[(I)*4+2], (C)[4], (C)[5]);               \
    upk2((ACC)[(I)*4+3], (C)[6], (C)[7]);               \
  } while(0)

// acc[64,256] (+)= sA[64, K=256] @ W[256 x 256cols], W row stride = ldw floats.
// acc: 16 u64 per thread: acc[i*4+j] = cols (tx*8+2j, +1), row ty*4+i.
__device__ __forceinline__ void mm256(u64* __restrict__ acc,
                                      const float* __restrict__ sA,
                                      const float* __restrict__ gW, int ldw,
                                      float* __restrict__ sW,
                                      int tid, int ty, int tx)
{
  const int e  = tid * 4;      // this thread's 4-float chunk within an 8x256 slab
  const int er = e >> 8;
  const int ec = e & 255;
  // prefetch slab 0 into buffer 0
  cp16(sW + e, gW + er * ldw + ec);
  cpcommit();

  const float* Abase = sA + ty * 4 * LDA;
  const int wcol = tx * 8;

  for (int s = 0; s < 32; ++s){
    cpwait0();
    __syncthreads();
    if (s < 31){
      float* dst = sW + ((s + 1) & 1) * (KS * 256);
      cp16(dst + e, gW + (s + 1) * KS * ldw + er * ldw + ec);
      cpcommit();
    }
    const float* w = sW + (s & 1) * (KS * 256) + wcol;
    const float* A = Abase + s * KS;
#pragma unroll
    for (int k4 = 0; k4 < KS; k4 += 4){
      float4 av[4];
#pragma unroll
      for (int i = 0; i < 4; ++i)
        av[i] = *(const float4*)(A + i * LDA + k4);    // warp-uniform broadcast
#pragma unroll
      for (int t = 0; t < 4; ++t){
        const float* wr = w + (k4 + t) * 256;
        ulonglong2 wp0 = *(const ulonglong2*)(wr);     // cols n0..n0+3 as 2 f32x2
        ulonglong2 wp1 = *(const ulonglong2*)(wr + 4); // cols n0+4..n0+7
#pragma unroll
        for (int i = 0; i < 4; ++i){
          float a = (t == 0) ? av[i].x : (t == 1) ? av[i].y : (t == 2) ? av[i].z : av[i].w;
          u64 a2 = pk2(a, a);
          fma2(acc[i*4+0], a2, wp0.x);
          fma2(acc[i*4+1], a2, wp0.y);
          fma2(acc[i*4+2], a2, wp1.x);
          fma2(acc[i*4+3], a2, wp1.y);
        }
      }
    }
  }
}

__global__ void __launch_bounds__(NT, 1)
trm_fused_kernel(const float* __restrict__ x,
                 const float* __restrict__ W_in,   const float* __restrict__ b_in,
                 const float* __restrict__ y_init,
                 const float* __restrict__ W_up,   const float* __restrict__ b_up,
                 const float* __restrict__ W_down, const float* __restrict__ b_down,
                 const float* __restrict__ ln_w,   const float* __restrict__ ln_b,
                 const float* __restrict__ W_comb, const float* __restrict__ b_comb,
                 const float* __restrict__ W_yt,   const float* __restrict__ b_yt,
                 const float* __restrict__ W_head, const float* __restrict__ b_head,
                 float* __restrict__ out)
{
  extern __shared__ float sm[];
  float* sZ = sm;                 // [64][256]
  float* sY = sZ + MT * LDA;      // [64][256]
  float* sH = sY + MT * LDA;      // [64][256]
  float* sW = sH + MT * LDA;      // 2 slabs of [8][256]

  const int tid = threadIdx.x;
  const int tx  = tid & 31;
  const int ty  = tid >> 5;       // warp id 0..15, owns rows 4*ty..4*ty+3
  const int n0  = tx * 8;
  const int r0  = blockIdx.x * MT;

  // ---- load x tile into sZ ----
  for (int e = tid * 4; e < MT * 256; e += NT * 4){
    int r = e >> 8, c = e & 255;
    *(float4*)(sZ + r * LDA + c) = *(const float4*)(x + (size_t)(r0 + r) * 256 + c);
  }
  __syncthreads();

  // ---- z = x @ W_in + b_in ; y = y_init ----
  {
    u64 acc[16];
#pragma unroll
    for (int i = 0; i < 16; ++i) acc[i] = 0ull;
    mm256(acc, sZ, W_in, 256, sW, tid, ty, tx);
    __syncthreads();                    // all reads of sZ (x data) done before overwrite
    float bi[8], yv[8];
#pragma unroll
    for (int j = 0; j < 8; ++j){ bi[j] = b_in[n0 + j]; yv[j] = y_init[n0 + j]; }
#pragma unroll
    for (int i = 0; i < 4; ++i){
      float C[8]; UNPACK8(acc, i, C);
      float* zr = sZ + (ty * 4 + i) * LDA + n0;
      float* yr = sY + (ty * 4 + i) * LDA + n0;
#pragma unroll
      for (int j = 0; j < 8; ++j){ zr[j] = C[j] + bi[j]; yr[j] = yv[j]; }
    }
    __syncthreads();
  }

  // ---- 3 H-cycles ----
  for (int hc = 0; hc < 3; ++hc){
    // ---- 6 L-cycles ----
    for (int lc = 0; lc < 6; ++lc){
      u64 accD[16];
#pragma unroll
      for (int i = 0; i < 16; ++i) accD[i] = 0ull;

      // h = gelu(z @ W_up + b_up) in 4 chunks of 256 cols; accD += h_chunk @ W_down_chunk
      for (int c = 0; c < 4; ++c){
        u64 accU[16];
#pragma unroll
        for (int i = 0; i < 16; ++i) accU[i] = 0ull;
        mm256(accU, sZ, W_up + c * 256, 1024, sW, tid, ty, tx);
        float bu[8];
#pragma unroll
        for (int j = 0; j < 8; ++j) bu[j] = b_up[c * 256 + n0 + j];
#pragma unroll
        for (int i = 0; i < 4; ++i){
          float C[8]; UNPACK8(accU, i, C);
          float* hr = sH + (ty * 4 + i) * LDA + n0;
#pragma unroll
          for (int j = 0; j < 8; ++j) hr[j] = gelu_exact(C[j] + bu[j]);
        }
        // down-proj chunk: first internal __syncthreads of mm256 orders the sH writes
        mm256(accD, sH, W_down + c * 256 * 256, 256, sW, tid, ty, tx);
      }

      // ---- residual + LayerNorm, write back to sZ ----
      __syncthreads();
      float bd[8], lw[8], lb[8];
#pragma unroll
      for (int j = 0; j < 8; ++j){
        bd[j] = b_down[n0 + j]; lw[j] = ln_w[n0 + j]; lb[j] = ln_b[n0 + j];
      }
      float T[4][8], ps[4], pq[4];
#pragma unroll
      for (int i = 0; i < 4; ++i){
        float C[8]; UNPACK8(accD, i, C);
        const float* zr = sZ + (ty * 4 + i) * LDA + n0;
        float s = 0.f, q = 0.f;
#pragma unroll
        for (int j = 0; j < 8; ++j){
          float v = zr[j] + C[j] + bd[j];
          T[i][j] = v; s += v; q += v * v;
        }
        ps[i] = s; pq[i] = q;
      }
#pragma unroll
      for (int off = 16; off > 0; off >>= 1){
#pragma unroll
        for (int i = 0; i < 4; ++i){
          ps[i] += __shfl_xor_sync(0xffffffffu, ps[i], off);
          pq[i] += __shfl_xor_sync(0xffffffffu, pq[i], off);
        }
      }
#pragma unroll
      for (int i = 0; i < 4; ++i){
        float mu  = ps[i] * (1.0f / 256.0f);
        float var = pq[i] * (1.0f / 256.0f) - mu * mu;
        float rs  = rsqrtf(var + LN_EPS_F);
        float* zr = sZ + (ty * 4 + i) * LDA + n0;
#pragma unroll
        for (int j = 0; j < 8; ++j)
          zr[j] = (T[i][j] - mu) * rs * lw[j] + lb[j];
      }
      __syncthreads();
    }

    // ---- combine: h = gelu([z|y] @ W_comb + b_comb); y += h @ W_yt + b_yt ----
    {
      u64 acc[16];
#pragma unroll
      for (int i = 0; i < 16; ++i) acc[i] = 0ull;
      mm256(acc, sZ, W_comb,             256, sW, tid, ty, tx);
      mm256(acc, sY, W_comb + 256 * 256, 256, sW, tid, ty, tx);
      float bc[8];
#pragma unroll
      for (int j = 0; j < 8; ++j) bc[j] = b_comb[n0 + j];
#pragma unroll
      for (int i = 0; i < 4; ++i){
        float C[8]; UNPACK8(acc, i, C);
        float* hr = sH + (ty * 4 + i) * LDA + n0;
#pragma unroll
        for (int j = 0; j < 8; ++j) hr[j] = gelu_exact(C[j] + bc[j]);
      }
      u64 acc2[16];
#pragma unroll
      for (int i = 0; i < 16; ++i) acc2[i] = 0ull;
      mm256(acc2, sH, W_yt, 256, sW, tid, ty, tx);
      __syncthreads();
      float by[8];
#pragma unroll
      for (int j = 0; j < 8; ++j) by[j] = b_yt[n0 + j];
#pragma unroll
      for (int i = 0; i < 4; ++i){
        float C[8]; UNPACK8(acc2, i, C);
        float* yr = sY + (ty * 4 + i) * LDA + n0;
#pragma unroll
        for (int j = 0; j < 8; ++j) yr[j] += C[j] + by[j];
      }
      __syncthreads();
    }
  }

  // ---- head: out = y @ W_head + b_head  (N=10) ----
  __syncthreads();
  for (int e = tid; e < MT * 10; e += NT){
    int m = e / 10;
    int n = e - m * 10;
    float s = b_head[n];
    const float* yr = sY + m * LDA;
    for (int k = 0; k < 256; ++k)
      s += yr[k] * W_head[k * 10 + n];
    out[(size_t)(r0 + m) * 10 + n] = s;
  }
}

extern "C" void kernel_launch(void* const* d_in, const int* in_sizes, int n_in,
                              void* d_out, int out_size)
{
  const float* x      = (const float*)d_in[0];
  const float* W_in   = (const float*)d_in[1];
  const float* b_in   = (const float*)d_in[2];
  const float* y_init = (const float*)d_in[3];
  const float* W_up   = (const float*)d_in[4];
  const float* b_up   = (const float*)d_in[5];
  const float* W_down = (const float*)d_in[6];
  const float* b_down = (const float*)d_in[7];
  const float* ln_w   = (const float*)d_in[8];
  const float* ln_b   = (const float*)d_in[9];
  const float* W_comb = (const float*)d_in[10];
  const float* b_comb = (const float*)d_in[11];
  const float* W_yt   = (const float*)d_in[12];
  const float* b_yt   = (const float*)d_in[13];
  const float* W_head = (const float*)d_in[14];
  const float* b_head = (const float*)d_in[15];
  float* out = (float*)d_out;

  const int B = in_sizes[0] / 256;           // rows
  const size_t smem = (size_t)(3 * MT * LDA + 2 * KS * 256) * sizeof(float); // 212992 B

  cudaFuncSetAttribute(trm_fused_kernel,
                       cudaFuncAttributeMaxDynamicSharedMemorySize, (int)smem);

  trm_fused_kernel<<<B / MT, NT, smem>>>(
      x, W_in, b_in, y_init, W_up, b_up, W_down, b_down,
      ln_w, ln_b, W_comb, b_comb, W_yt, b_yt, W_head, b_head, out);
}

// round 14
// speedup vs baseline: 1.0581x; 1.0007x over previous
#include <cuda_runtime.h>
#include <math.h>

// StandardTRM fused fp32 kernel, v2.
// Tile = 64 rows, 512 threads (16 warps, 4/SMSP), thread microtile = 4x8.
// Warp w owns rows 4w..4w+3 entirely -> LayerNorm is a pure warp-shuffle reduce.
// z,y,h tiles live in SMEM for the whole 18-layer + 3-combine chain.
// Weights streamed from L2 via double-buffered cp.async slabs (8 rows x 256 cols).
// Inner product uses packed fma.rn.f32x2; W operands loaded as ulonglong2 so the
// LDS.128 result pairs feed fma.f32x2 directly (no repack movs).

#define MT   64          // rows per CTA tile
#define LDA  256         // row stride (floats) for SMEM tiles
#define KS   8           // K rows per weight slab
#define NT   512         // threads per CTA
#define LN_EPS_F 1e-5f

typedef unsigned long long u64;

__device__ __forceinline__ u64 pk2(float x, float y){
  u64 r; asm("mov.b64 %0, {%1, %2};" : "=l"(r) : "f"(x), "f"(y)); return r;
}
__device__ __forceinline__ void upk2(u64 v, float& x, float& y){
  asm("mov.b64 {%0, %1}, %2;" : "=f"(x), "=f"(y) : "l"(v));
}
__device__ __forceinline__ void fma2(u64& c, u64 a, u64 b){
  asm("fma.rn.f32x2 %0, %1, %2, %0;" : "+l"(c) : "l"(a), "l"(b));
}
__device__ __forceinline__ void cp16(float* s, const float* g){
  unsigned a = (unsigned)__cvta_generic_to_shared(s);
  asm volatile("cp.async.cg.shared.global [%0], [%1], 16;" :: "r"(a), "l"(g));
}
__device__ __forceinline__ void cpcommit(){ asm volatile("cp.async.commit_group;" ::: "memory"); }
__device__ __forceinline__ void cpwait0(){ asm volatile("cp.async.wait_group 0;" ::: "memory"); }

__device__ __forceinline__ float gelu_exact(float v){
  return 0.5f * v * (1.0f + erff(v * 0.7071067811865475f));
}

#define UNPACK8(ACC, I, C) do {                         \
    upk2((ACC)[(I)*4+0], (C)[0], (C)[1]);               \
    upk2((ACC)[(I)*4+1], (C)[2], (C)[3]);               \
    upk2((ACC)[(I)*4+2], (C)[4], (C)[5]);               \
    upk2((ACC)[(I)*4+3], (C)[6], (C)[7]);               \
  } while(0)

// acc[64,256] (+)= sA[64, K=256] @ W[256 x 256cols], W row stride = ldw floats.
// acc: 16 u64 per thread: acc[i*4+j] = cols (tx*8+2j, +1), row ty*4+i.
__device__ __forceinline__ void mm256(u64* __restrict__ acc,
                                      const float* __restrict__ sA,
                                      const float* __restrict__ gW, int ldw,
                                      float* __restrict__ sW,
                                      int tid, int ty, int tx)
{
  const int e  = tid * 4;      // this thread's 4-float chunk within an 8x256 slab
  const int er = e >> 8;
  const int ec = e & 255;
  // prefetch slab 0 into buffer 0
  cp16(sW + e, gW + er * ldw + ec);
  cpcommit();

  const float* Abase = sA + ty * 4 * LDA;
  const int wcol = tx * 8;

  for (int s = 0; s < 32; ++s){
    cpwait0();
    __syncthreads();
    if (s < 31){
      float* dst = sW + ((s + 1) & 1) * (KS * 256);
      cp16(dst + e, gW + (s + 1) * KS * ldw + er * ldw + ec);
      cpcommit();
    }
    const float* w = sW + (s & 1) * (KS * 256) + wcol;
    const float* A = Abase + s * KS;
#pragma unroll
    for (int k4 = 0; k4 < KS; k4 += 4){
      float4 av[4];
#pragma unroll
      for (int i = 0; i < 4; ++i)
        av[i] = *(const float4*)(A + i * LDA + k4);    // warp-uniform broadcast
#pragma unroll
      for (int t = 0; t < 4; ++t){
        const float* wr = w + (k4 + t) * 256;
        ulonglong2 wp0 = *(const ulonglong2*)(wr);     // cols n0..n0+3 as 2 f32x2
        ulonglong2 wp1 = *(const ulonglong2*)(wr + 4); // cols n0+4..n0+7
#pragma unroll
        for (int i = 0; i < 4; ++i){
          float a = (t == 0) ? av[i].x : (t == 1) ? av[i].y : (t == 2) ? av[i].z : av[i].w;
          u64 a2 = pk2(a, a);
          fma2(acc[i*4+0], a2, wp0.x);
          fma2(acc[i*4+1], a2, wp0.y);
          fma2(acc[i*4+2], a2, wp1.x);
          fma2(acc[i*4+3], a2, wp1.y);
        }
      }
    }
  }
}

__global__ void __launch_bounds__(NT, 1)
trm_fused_kernel(const float* __restrict__ x,
                 const float* __restrict__ W_in,   const float* __restrict__ b_in,
                 const float* __restrict__ y_init,
                 const float* __restrict__ W_up,   const float* __restrict__ b_up,
                 const float* __restrict__ W_down, const float* __restrict__ b_down,
                 const float* __restrict__ ln_w,   const float* __restrict__ ln_b,
                 const float* __restrict__ W_comb, const float* __restrict__ b_comb,
                 const float* __restrict__ W_yt,   const float* __restrict__ b_yt,
                 const float* __restrict__ W_head, const float* __restrict__ b_head,
                 float* __restrict__ out)
{
  extern __shared__ float sm[];
  float* sZ = sm;                 // [64][256]
  float* sY = sZ + MT * LDA;      // [64][256]
  float* sH = sY + MT * LDA;      // [64][256]
  float* sW = sH + MT * LDA;      // 2 slabs of [8][256]

  const int tid = threadIdx.x;
  const int tx  = tid & 31;
  const int ty  = tid >> 5;       // warp id 0..15, owns rows 4*ty..4*ty+3
  const int n0  = tx * 8;
  const int r0  = blockIdx.x * MT;

  // ---- load x tile into sZ ----
  for (int e = tid * 4; e < MT * 256; e += NT * 4){
    int r = e >> 8, c = e & 255;
    *(float4*)(sZ + r * LDA + c) = *(const float4*)(x + (size_t)(r0 + r) * 256 + c);
  }
  __syncthreads();

  // ---- z = x @ W_in + b_in ; y = y_init ----
  {
    u64 acc[16];
#pragma unroll
    for (int i = 0; i < 16; ++i) acc[i] = 0ull;
    mm256(acc, sZ, W_in, 256, sW, tid, ty, tx);
    __syncthreads();                    // all reads of sZ (x data) done before overwrite
    float bi[8], yv[8];
#pragma unroll
    for (int j = 0; j < 8; ++j){ bi[j] = b_in[n0 + j]; yv[j] = y_init[n0 + j]; }
#pragma unroll
    for (int i = 0; i < 4; ++i){
      float C[8]; UNPACK8(acc, i, C);
      float* zr = sZ + (ty * 4 + i) * LDA + n0;
      float* yr = sY + (ty * 4 + i) * LDA + n0;
#pragma unroll
      for (int j = 0; j < 8; ++j){ zr[j] = C[j] + bi[j]; yr[j] = yv[j]; }
    }
    __syncthreads();
  }

  // ---- 3 H-cycles ----
  for (int hc = 0; hc < 3; ++hc){
    // ---- 6 L-cycles ----
    for (int lc = 0; lc < 6; ++lc){
      u64 accD[16];
#pragma unroll
      for (int i = 0; i < 16; ++i) accD[i] = 0ull;

      // h = gelu(z @ W_up + b_up) in 4 chunks of 256 cols; accD += h_chunk @ W_down_chunk
      for (int c = 0; c < 4; ++c){
        u64 accU[16];
#pragma unroll
        for (int i = 0; i < 16; ++i) accU[i] = 0ull;
        mm256(accU, sZ, W_up + c * 256, 1024, sW, tid, ty, tx);
        float bu[8];
#pragma unroll
        for (int j = 0; j < 8; ++j) bu[j] = b_up[c * 256 + n0 + j];
#pragma unroll
        for (int i = 0; i < 4; ++i){
          float C[8]; UNPACK8(accU, i, C);
          float* hr = sH + (ty * 4 + i) * LDA + n0;
#pragma unroll
          for (int j = 0; j < 8; ++j) hr[j] = gelu_exact(C[j] + bu[j]);
        }
        // down-proj chunk: first internal __syncthreads of mm256 orders the sH writes
        mm256(accD, sH, W_down + c * 256 * 256, 256, sW, tid, ty, tx);
      }

      // ---- residual + LayerNorm, write back to sZ ----
      __syncthreads();
      float bd[8], lw[8], lb[8];
#pragma unroll
      for (int j = 0; j < 8; ++j){
        bd[j] = b_down[n0 + j]; lw[j] = ln_w[n0 + j]; lb[j] = ln_b[n0 + j];
      }
      float T[4][8], ps[4], pq[4];
#pragma unroll
      for (int i = 0; i < 4; ++i){
        float C[8]; UNPACK8(accD, i, C);
        const float* zr = sZ + (ty * 4 + i) * LDA + n0;
        float s = 0.f, q = 0.f;
#pragma unroll
        for (int j = 0; j < 8; ++j){
          float v = zr[j] + C[j] + bd[j];
          T[i][j] = v; s += v; q += v * v;
        }
        ps[i] = s; pq[i] = q;
      }
#pragma unroll
      for (int off = 16; off > 0; off >>= 1){
#pragma unroll
        for (int i = 0; i < 4; ++i){
          ps[i] += __shfl_xor_sync(0xffffffffu, ps[i], off);
          pq[i] += __shfl_xor_sync(0xffffffffu, pq[i], off);
        }
      }
#pragma unroll
      for (int i = 0; i < 4; ++i){
        float mu  = ps[i] * (1.0f / 256.0f);
        float var = pq[i] * (1.0f / 256.0f) - mu * mu;
        float rs  = rsqrtf(var + LN_EPS_F);
        float* zr = sZ + (ty * 4 + i) * LDA + n0;
#pragma unroll
        for (int j = 0; j < 8; ++j)
          zr[j] = (T[i][j] - mu) * rs * lw[j] + lb[j];
      }
      __syncthreads();
    }

    // ---- combine: h = gelu([z|y] @ W_comb + b_comb); y += h @ W_yt + b_yt ----
    {
      u64 acc[16];
#pragma unroll
      for (int i = 0; i < 16; ++i) acc[i] = 0ull;
      mm256(acc, sZ, W_comb,             256, sW, tid, ty, tx);
      mm256(acc, sY, W_comb + 256 * 256, 256, sW, tid, ty, tx);
      float bc[8];
#pragma unroll
      for (int j = 0; j < 8; ++j) bc[j] = b_comb[n0 + j];
#pragma unroll
      for (int i = 0; i < 4; ++i){
        float C[8]; UNPACK8(acc, i, C);
        float* hr = sH + (ty * 4 + i) * LDA + n0;
#pragma unroll
        for (int j = 0; j < 8; ++j) hr[j] = gelu_exact(C[j] + bc[j]);
      }
      u64 acc2[16];
#pragma unroll
      for (int i = 0; i < 16; ++i) acc2[i] = 0ull;
      mm256(acc2, sH, W_yt, 256, sW, tid, ty, tx);
      __syncthreads();
      float by[8];
#pragma unroll
      for (int j = 0; j < 8; ++j) by[j] = b_yt[n0 + j];
#pragma unroll
      for (int i = 0; i < 4; ++i){
        float C[8]; UNPACK8(acc2, i, C);
        float* yr = sY + (ty * 4 + i) * LDA + n0;
#pragma unroll
        for (int j = 0; j < 8; ++j) yr[j] += C[j] + by[j];
      }
      __syncthreads();
    }
  }

  // ---- head: out = y @ W_head + b_head  (N=10) ----
  __syncthreads();
  for (int e = tid; e < MT * 10; e += NT){
    int m = e / 10;
    int n = e - m * 10;
    float s = b_head[n];
    const float* yr = sY + m * LDA;
    for (int k = 0; k < 256; ++k)
      s += yr[k] * W_head[k * 10 + n];
    out[(size_t)(r0 + m) * 10 + n] = s;
  }
}

extern "C" void kernel_launch(void* const* d_in, const int* in_sizes, int n_in,
                              void* d_out, int out_size)
{
  const float* x      = (const float*)d_in[0];
  const float* W_in   = (const float*)d_in[1];
  const float* b_in   = (const float*)d_in[2];
  const float* y_init = (const float*)d_in[3];
  const float* W_up   = (const float*)d_in[4];
  const float* b_up   = (const float*)d_in[5];
  const float* W_down = (const float*)d_in[6];
  const float* b_down = (const float*)d_in[7];
  const float* ln_w   = (const float*)d_in[8];
  const float* ln_b   = (const float*)d_in[9];
  const float* W_comb = (const float*)d_in[10];
  const float* b_comb = (const float*)d_in[11];
  const float* W_yt   = (const float*)d_in[12];
  const float* b_yt   = (const float*)d_in[13];
  const float* W_head = (const float*)d_in[14];
  const float* b_head = (const float*)d_in[15];
  float* out = (float*)d_out;

  const int B = in_sizes[0] / 256;           // rows
  const size_t smem = (size_t)(3 * MT * LDA + 2 * KS * 256) * sizeof(float); // 212992 B

  cudaFuncSetAttribute(trm_fused_kernel,
                       cudaFuncAttributeMaxDynamicSharedMemorySize, (int)smem);

  trm_fused_kernel<<<B / MT, NT, smem>>>(
      x, W_in, b_in, y_init, W_up, b_up, W_down, b_down,
      ln_w, ln_b, W_comb, b_comb, W_yt, b_yt, W_head, b_head, out);
}

// round 15
// speedup vs baseline: 1.4841x; 1.4027x over previous
#include <cuda_runtime.h>
#include <math.h>

// StandardTRM fused fp32 kernel, v3.
// Back to v1 shape: tile = 64 rows, 256 threads (8 warps), microtile 8x8
// (best FMA-per-LDS ratio), warp w owns rows 8w..8w+7 -> LayerNorm is a pure
// warp-shuffle reduction. z,y,h tiles live in SMEM for the whole chain;
// weights stream from L2 via double-buffered cp.async slabs (8 rows x 256).
// NEW in v3: software-pipelined operand loads inside the k-loop -- W register
// pairs for step t+1 load before the 32 fma2 of step t, and the A float4
// group for the next k4 loads two steps early, so no LDS result is consumed
// inside its 29-cycle latency shadow (the v1 bottleneck).

#define MT   64          // rows per CTA tile
#define LDA  256         // row stride (floats) for SMEM tiles
#define KS   8           // K rows per weight slab
#define NT   256         // threads per CTA
#define LN_EPS_F 1e-5f

typedef unsigned long long u64;

__device__ __forceinline__ u64 pk2(float x, float y){
  u64 r; asm("mov.b64 %0, {%1, %2};" : "=l"(r) : "f"(x), "f"(y)); return r;
}
__device__ __forceinline__ void upk2(u64 v, float& x, float& y){
  asm("mov.b64 {%0, %1}, %2;" : "=f"(x), "=f"(y) : "l"(v));
}
__device__ __forceinline__ void fma2(u64& c, u64 a, u64 b){
  asm("fma.rn.f32x2 %0, %1, %2, %0;" : "+l"(c) : "l"(a), "l"(b));
}
__device__ __forceinline__ void cp16(float* s, const float* g){
  unsigned a = (unsigned)__cvta_generic_to_shared(s);
  asm volatile("cp.async.cg.shared.global [%0], [%1], 16;" :: "r"(a), "l"(g));
}
__device__ __forceinline__ void cpcommit(){ asm volatile("cp.async.commit_group;" ::: "memory"); }
__device__ __forceinline__ void cpwait0(){ asm volatile("cp.async.wait_group 0;" ::: "memory"); }

__device__ __forceinline__ float gelu_exact(float v){
  return 0.5f * v * (1.0f + erff(v * 0.7071067811865475f));
}

#define UNPACK8(ACC, I, C) do {                         \
    upk2((ACC)[(I)*4+0], (C)[0], (C)[1]);               \
    upk2((ACC)[(I)*4+1], (C)[2], (C)[3]);               \
    upk2((ACC)[(I)*4+2], (C)[4], (C)[5]);               \
    upk2((ACC)[(I)*4+3], (C)[6], (C)[7]);               \
  } while(0)

// acc[64,256] (+)= sA[64, K=256] @ W[256 x 256cols], W row stride = ldw floats.
// acc: 32 u64 (f32x2) per thread: acc[i*4+j] = cols (tx*8+2j, +1), row ty*8+i.
__device__ __forceinline__ void mm256(u64* __restrict__ acc,
                                      const float* __restrict__ sA,
                                      const float* __restrict__ gW, int ldw,
                                      float* __restrict__ sW,
                                      int tid, int ty, int tx)
{
  const int e  = tid * 8;      // this thread's 8-float chunk within an 8x256 slab
  const int er = e >> 8;
  const int ec = e & 255;
  // prefetch slab 0 into buffer 0
  {
    const float* src = gW + er * ldw + ec;
    cp16(sW + e,     src);
    cp16(sW + e + 4, src + 4);
    cpcommit();
  }
  const float* Abase = sA + ty * 8 * LDA;
  const int wcol = tx * 8;

  for (int s = 0; s < 32; ++s){
    cpwait0();
    __syncthreads();
    if (s < 31){
      float* dst = sW + ((s + 1) & 1) * (KS * 256);
      const float* src = gW + (s + 1) * KS * ldw + er * ldw + ec;
      cp16(dst + e,     src);
      cp16(dst + e + 4, src + 4);
      cpcommit();
    }
    const float* w = sW + (s & 1) * (KS * 256) + wcol;
    const float* A = Abase + s * KS;

    // ---- software-pipelined 8 k-steps ----
    float4 avc[8], avn[8];
#pragma unroll
    for (int i = 0; i < 8; ++i)
      avc[i] = *(const float4*)(A + i * LDA);          // k 0..3, broadcast
    ulonglong2 wp0 = *(const ulonglong2*)(w);          // W row for t=0
    ulonglong2 wp1 = *(const ulonglong2*)(w + 4);

#pragma unroll
    for (int t = 0; t < 8; ++t){
      ulonglong2 np0, np1;
      if (t < 7){                                      // prefetch W row t+1
        const float* wr = w + (t + 1) * 256;
        np0 = *(const ulonglong2*)(wr);
        np1 = *(const ulonglong2*)(wr + 4);
      }
      if (t == 2){                                     // prefetch A k 4..7
#pragma unroll
        for (int i = 0; i < 8; ++i)
          avn[i] = *(const float4*)(A + i * LDA + 4);
      }
      const int tt = t & 3;
#pragma unroll
      for (int i = 0; i < 8; ++i){
        const float4& v = (t < 4) ? avc[i] : avn[i];
        float a = (tt == 0) ? v.x : (tt == 1) ? v.y : (tt == 2) ? v.z : v.w;
        u64 a2 = pk2(a, a);
        fma2(acc[i*4+0], a2, wp0.x);
        fma2(acc[i*4+1], a2, wp0.y);
        fma2(acc[i*4+2], a2, wp1.x);
        fma2(acc[i*4+3], a2, wp1.y);
      }
      if (t < 7){ wp0 = np0; wp1 = np1; }
    }
  }
}

__global__ void __launch_bounds__(NT, 1)
trm_fused_kernel(const float* __restrict__ x,
                 const float* __restrict__ W_in,   const float* __restrict__ b_in,
                 const float* __restrict__ y_init,
                 const float* __restrict__ W_up,   const float* __restrict__ b_up,
                 const float* __restrict__ W_down, const float* __restrict__ b_down,
                 const float* __restrict__ ln_w,   const float* __restrict__ ln_b,
                 const float* __restrict__ W_comb, const float* __restrict__ b_comb,
                 const float* __restrict__ W_yt,   const float* __restrict__ b_yt,
                 const float* __restrict__ W_head, const float* __restrict__ b_head,
                 float* __restrict__ out)
{
  extern __shared__ float sm[];
  float* sZ = sm;                 // [64][256]
  float* sY = sZ + MT * LDA;      // [64][256]
  float* sH = sY + MT * LDA;      // [64][256]
  float* sW = sH + MT * LDA;      // 2 slabs of [8][256]

  const int tid = threadIdx.x;
  const int tx  = tid & 31;
  const int ty  = tid >> 5;       // warp id, owns rows 8*ty..8*ty+7
  const int n0  = tx * 8;
  const int r0  = blockIdx.x * MT;

  // ---- load x tile into sZ ----
  for (int e = tid * 4; e < MT * 256; e += NT * 4){
    int r = e >> 8, c = e & 255;
    *(float4*)(sZ + r * LDA + c) = *(const float4*)(x + (size_t)(r0 + r) * 256 + c);
  }
  __syncthreads();

  // ---- z = x @ W_in + b_in ; y = y_init ----
  {
    u64 acc[32];
#pragma unroll
    for (int i = 0; i < 32; ++i) acc[i] = 0ull;
    mm256(acc, sZ, W_in, 256, sW, tid, ty, tx);
    __syncthreads();                    // all reads of sZ (x data) done before overwrite
    float bi[8], yv[8];
#pragma unroll
    for (int j = 0; j < 8; ++j){ bi[j] = b_in[n0 + j]; yv[j] = y_init[n0 + j]; }
#pragma unroll
    for (int i = 0; i < 8; ++i){
      float C[8]; UNPACK8(acc, i, C);
      float* zr = sZ + (ty * 8 + i) * LDA + n0;
      float* yr = sY + (ty * 8 + i) * LDA + n0;
#pragma unroll
      for (int j = 0; j < 8; ++j){ zr[j] = C[j] + bi[j]; yr[j] = yv[j]; }
    }
    __syncthreads();
  }

  // ---- 3 H-cycles ----
  for (int hc = 0; hc < 3; ++hc){
    // ---- 6 L-cycles ----
    for (int lc = 0; lc < 6; ++lc){
      u64 accD[32];
#pragma unroll
      for (int i = 0; i < 32; ++i) accD[i] = 0ull;

      // h = gelu(z @ W_up + b_up) in 4 chunks of 256 cols; accD += h_chunk @ W_down_chunk
      for (int c = 0; c < 4; ++c){
        u64 accU[32];
#pragma unroll
        for (int i = 0; i < 32; ++i) accU[i] = 0ull;
        mm256(accU, sZ, W_up + c * 256, 1024, sW, tid, ty, tx);
        float bu[8];
#pragma unroll
        for (int j = 0; j < 8; ++j) bu[j] = b_up[c * 256 + n0 + j];
#pragma unroll
        for (int i = 0; i < 8; ++i){
          float C[8]; UNPACK8(accU, i, C);
          float* hr = sH + (ty * 8 + i) * LDA + n0;
#pragma unroll
          for (int j = 0; j < 8; ++j) hr[j] = gelu_exact(C[j] + bu[j]);
        }
        // down-proj chunk: first internal __syncthreads of mm256 orders the sH writes
        mm256(accD, sH, W_down + c * 256 * 256, 256, sW, tid, ty, tx);
      }

      // ---- residual + LayerNorm, write back to sZ ----
      __syncthreads();
      float bd[8], lw[8], lb[8];
#pragma unroll
      for (int j = 0; j < 8; ++j){
        bd[j] = b_down[n0 + j]; lw[j] = ln_w[n0 + j]; lb[j] = ln_b[n0 + j];
      }
      float T[8][8], ps[8], pq[8];
#pragma unroll
      for (int i = 0; i < 8; ++i){
        float C[8]; UNPACK8(accD, i, C);
        const float* zr = sZ + (ty * 8 + i) * LDA + n0;
        float s = 0.f, q = 0.f;
#pragma unroll
        for (int j = 0; j < 8; ++j){
          float v = zr[j] + C[j] + bd[j];
          T[i][j] = v; s += v; q += v * v;
        }
        ps[i] = s; pq[i] = q;
      }
#pragma unroll
      for (int off = 16; off > 0; off >>= 1){
#pragma unroll
        for (int i = 0; i < 8; ++i){
          ps[i] += __shfl_xor_sync(0xffffffffu, ps[i], off);
          pq[i] += __shfl_xor_sync(0xffffffffu, pq[i], off);
        }
      }
#pragma unroll
      for (int i = 0; i < 8; ++i){
        float mu  = ps[i] * (1.0f / 256.0f);
        float var = pq[i] * (1.0f / 256.0f) - mu * mu;
        float rs  = rsqrtf(var + LN_EPS_F);
        float* zr = sZ + (ty * 8 + i) * LDA + n0;
#pragma unroll
        for (int j = 0; j < 8; ++j)
          zr[j] = (T[i][j] - mu) * rs * lw[j] + lb[j];
      }
      __syncthreads();
    }

    // ---- combine: h = gelu([z|y] @ W_comb + b_comb); y += h @ W_yt + b_yt ----
    {
      u64 acc[32];
#pragma unroll
      for (int i = 0; i < 32; ++i) acc[i] = 0ull;
      mm256(acc, sZ, W_comb,             256, sW, tid, ty, tx);
      mm256(acc, sY, W_comb + 256 * 256, 256, sW, tid, ty, tx);
      float bc[8];
#pragma unroll
      for (int j = 0; j < 8; ++j) bc[j] = b_comb[n0 + j];
#pragma unroll
      for (int i = 0; i < 8; ++i){
        float C[8]; UNPACK8(acc, i, C);
        float* hr = sH + (ty * 8 + i) * LDA + n0;
#pragma unroll
        for (int j = 0; j < 8; ++j) hr[j] = gelu_exact(C[j] + bc[j]);
      }
      u64 acc2[32];
#pragma unroll
      for (int i = 0; i < 32; ++i) acc2[i] = 0ull;
      mm256(acc2, sH, W_yt, 256, sW, tid, ty, tx);
      __syncthreads();
      float by[8];
#pragma unroll
      for (int j = 0; j < 8; ++j) by[j] = b_yt[n0 + j];
#pragma unroll
      for (int i = 0; i < 8; ++i){
        float C[8]; UNPACK8(acc2, i, C);
        float* yr = sY + (ty * 8 + i) * LDA + n0;
#pragma unroll
        for (int j = 0; j < 8; ++j) yr[j] += C[j] + by[j];
      }
      __syncthreads();
    }
  }

  // ---- head: out = y @ W_head + b_head  (N=10) ----
  __syncthreads();
  for (int e = tid; e < MT * 10; e += NT){
    int m = e / 10;
    int n = e - m * 10;
    float s = b_head[n];
    const float* yr = sY + m * LDA;
    for (int k = 0; k < 256; ++k)
      s += yr[k] * W_head[k * 10 + n];
    out[(size_t)(r0 + m) * 10 + n] = s;
  }
}

extern "C" void kernel_launch(void* const* d_in, const int* in_sizes, int n_in,
                              void* d_out, int out_size)
{
  const float* x      = (const float*)d_in[0];
  const float* W_in   = (const float*)d_in[1];
  const float* b_in   = (const float*)d_in[2];
  const float* y_init = (const float*)d_in[3];
  const float* W_up   = (const float*)d_in[4];
  const float* b_up   = (const float*)d_in[5];
  const float* W_down = (const float*)d_in[6];
  const float* b_down = (const float*)d_in[7];
  const float* ln_w   = (const float*)d_in[8];
  const float* ln_b   = (const float*)d_in[9];
  const float* W_comb = (const float*)d_in[10];
  const float* b_comb = (const float*)d_in[11];
  const float* W_yt   = (const float*)d_in[12];
  const float* b_yt   = (const float*)d_in[13];
  const float* W_head = (const float*)d_in[14];
  const float* b_head = (const float*)d_in[15];
  float* out = (float*)d_out;

  const int B = in_sizes[0] / 256;           // rows
  const size_t smem = (size_t)(3 * MT * LDA + 2 * KS * 256) * sizeof(float); // 212992 B

  cudaFuncSetAttribute(trm_fused_kernel,
                       cudaFuncAttributeMaxDynamicSharedMemorySize, (int)smem);

  trm_fused_kernel<<<B / MT, NT, smem>>>(
      x, W_in, b_in, y_init, W_up, b_up, W_down, b_down,
      ln_w, ln_b, W_comb, b_comb, W_yt, b_yt, W_head, b_head, out);
}

// round 16
// speedup vs baseline: 1.6799x; 1.1319x over previous
#include <cuda_runtime.h>
#include <math.h>

// StandardTRM fused fp32 kernel, v4.
// Tile = 64 rows, 256 threads (8 warps), microtile 8 rows x 8 cols, but the
// 8 columns are now TWO 16-byte blocks: cols [tx*4..tx*4+3] and
// [128+tx*4..128+tx*4+3]. This makes every W shared-load and every epilogue
// store lane-contiguous (16B stride) -> ZERO bank conflicts. v1/v3 used one
// 32B block per lane (32B stride), a 2-way conflict on every LDS.128, which
// made the smem crossbar (144 cyc/k-step/SM) the binder over the fma pipe
// (128 cyc/k-step/SM). Also: weight slabs grow to 16 rows (16KB x2), halving
// barrier/cpwait count per matmul.

#define MT   64          // rows per CTA tile
#define LDA  256         // row stride (floats) for SMEM tiles
#define KS   16          // K rows per weight slab
#define NT   256         // threads per CTA
#define LN_EPS_F 1e-5f

typedef unsigned long long u64;

__device__ __forceinline__ u64 pk2(float x, float y){
  u64 r; asm("mov.b64 %0, {%1, %2};" : "=l"(r) : "f"(x), "f"(y)); return r;
}
__device__ __forceinline__ void upk2(u64 v, float& x, float& y){
  asm("mov.b64 {%0, %1}, %2;" : "=f"(x), "=f"(y) : "l"(v));
}
__device__ __forceinline__ void fma2(u64& c, u64 a, u64 b){
  asm("fma.rn.f32x2 %0, %1, %2, %0;" : "+l"(c) : "l"(a), "l"(b));
}
__device__ __forceinline__ void cp16(float* s, const float* g){
  unsigned a = (unsigned)__cvta_generic_to_shared(s);
  asm volatile("cp.async.cg.shared.global [%0], [%1], 16;" :: "r"(a), "l"(g));
}
__device__ __forceinline__ void cpcommit(){ asm volatile("cp.async.commit_group;" ::: "memory"); }
__device__ __forceinline__ void cpwait0(){ asm volatile("cp.async.wait_group 0;" ::: "memory"); }

__device__ __forceinline__ float gelu_exact(float v){
  return 0.5f * v * (1.0f + erff(v * 0.7071067811865475f));
}

// acc[i*4+0..1] = cols (c0, c0+1), (c0+2, c0+3); acc[i*4+2..3] = cols (+128).
#define UNPACK8(ACC, I, C) do {                         \
    upk2((ACC)[(I)*4+0], (C)[0], (C)[1]);               \
    upk2((ACC)[(I)*4+1], (C)[2], (C)[3]);               \
    upk2((ACC)[(I)*4+2], (C)[4], (C)[5]);               \
    upk2((ACC)[(I)*4+3], (C)[6], (C)[7]);               \
  } while(0)

// acc[64,256] (+)= sA[64, K=256] @ W[256 x 256cols], W row stride = ldw floats.
// Thread (ty,tx): rows ty*8..+7, cols {tx*4..+3} u {128+tx*4..+3}.
__device__ __forceinline__ void mm256(u64* __restrict__ acc,
                                      const float* __restrict__ sA,
                                      const float* __restrict__ gW, int ldw,
                                      float* __restrict__ sW,
                                      int tid, int ty, int tx)
{
  const int e  = tid * 16;     // this thread's 16-float chunk within a 16x256 slab
  const int er = e >> 8;
  const int ec = e & 255;
  // prefetch slab 0 into buffer 0
  {
    const float* src = gW + er * ldw + ec;
    cp16(sW + e,      src);
    cp16(sW + e + 4,  src + 4);
    cp16(sW + e + 8,  src + 8);
    cp16(sW + e + 12, src + 12);
    cpcommit();
  }
  const float* Abase = sA + ty * 8 * LDA;
  const int c0 = tx * 4;

  for (int s = 0; s < 16; ++s){
    cpwait0();
    __syncthreads();
    if (s < 15){
      float* dst = sW + ((s + 1) & 1) * (KS * 256);
      const float* src = gW + (s + 1) * KS * ldw + er * ldw + ec;
      cp16(dst + e,      src);
      cp16(dst + e + 4,  src + 4);
      cp16(dst + e + 8,  src + 8);
      cp16(dst + e + 12, src + 12);
      cpcommit();
    }
    const float* w = sW + (s & 1) * (KS * 256) + c0;
    const float* A = Abase + s * KS;
#pragma unroll
    for (int k4 = 0; k4 < KS; k4 += 4){
      float4 av[8];
#pragma unroll
      for (int i = 0; i < 8; ++i)
        av[i] = *(const float4*)(A + i * LDA + k4);    // warp-uniform broadcast
#pragma unroll
      for (int t = 0; t < 4; ++t){
        const float* wr = w + (k4 + t) * 256;
        ulonglong2 lo = *(const ulonglong2*)(wr);        // cols c0..c0+3  (16B stride, no conflicts)
        ulonglong2 hi = *(const ulonglong2*)(wr + 128);  // cols 128+c0..+3
#pragma unroll
        for (int i = 0; i < 8; ++i){
          float a = (t == 0) ? av[i].x : (t == 1) ? av[i].y : (t == 2) ? av[i].z : av[i].w;
          u64 a2 = pk2(a, a);
          fma2(acc[i*4+0], a2, lo.x);
          fma2(acc[i*4+1], a2, lo.y);
          fma2(acc[i*4+2], a2, hi.x);
          fma2(acc[i*4+3], a2, hi.y);
        }
      }
    }
  }
}

__global__ void __launch_bounds__(NT, 1)
trm_fused_kernel(const float* __restrict__ x,
                 const float* __restrict__ W_in,   const float* __restrict__ b_in,
                 const float* __restrict__ y_init,
                 const float* __restrict__ W_up,   const float* __restrict__ b_up,
                 const float* __restrict__ W_down, const float* __restrict__ b_down,
                 const float* __restrict__ ln_w,   const float* __restrict__ ln_b,
                 const float* __restrict__ W_comb, const float* __restrict__ b_comb,
                 const float* __restrict__ W_yt,   const float* __restrict__ b_yt,
                 const float* __restrict__ W_head, const float* __restrict__ b_head,
                 float* __restrict__ out)
{
  extern __shared__ float sm[];
  float* sZ = sm;                 // [64][256]
  float* sY = sZ + MT * LDA;      // [64][256]
  float* sH = sY + MT * LDA;      // [64][256]
  float* sW = sH + MT * LDA;      // 2 slabs of [16][256]

  const int tid = threadIdx.x;
  const int tx  = tid & 31;
  const int ty  = tid >> 5;       // warp id, owns rows 8*ty..8*ty+7
  const int c0  = tx * 4;         // first column block; second is c0+128
  const int r0  = blockIdx.x * MT;

  // ---- load x tile into sZ ----
  for (int e = tid * 4; e < MT * 256; e += NT * 4){
    int r = e >> 8, c = e & 255;
    *(float4*)(sZ + r * LDA + c) = *(const float4*)(x + (size_t)(r0 + r) * 256 + c);
  }
  __syncthreads();

  // ---- z = x @ W_in + b_in ; y = y_init ----
  {
    u64 acc[32];
#pragma unroll
    for (int i = 0; i < 32; ++i) acc[i] = 0ull;
    mm256(acc, sZ, W_in, 256, sW, tid, ty, tx);
    __syncthreads();                    // all reads of sZ (x data) done before overwrite
    float4 bi0 = *(const float4*)(b_in + c0);
    float4 bi1 = *(const float4*)(b_in + 128 + c0);
    float4 yv0 = *(const float4*)(y_init + c0);
    float4 yv1 = *(const float4*)(y_init + 128 + c0);
#pragma unroll
    for (int i = 0; i < 8; ++i){
      float C[8]; UNPACK8(acc, i, C);
      float* zr = sZ + (ty * 8 + i) * LDA;
      float* yr = sY + (ty * 8 + i) * LDA;
      *(float4*)(zr + c0)       = make_float4(C[0]+bi0.x, C[1]+bi0.y, C[2]+bi0.z, C[3]+bi0.w);
      *(float4*)(zr + 128 + c0) = make_float4(C[4]+bi1.x, C[5]+bi1.y, C[6]+bi1.z, C[7]+bi1.w);
      *(float4*)(yr + c0)       = yv0;
      *(float4*)(yr + 128 + c0) = yv1;
    }
    __syncthreads();
  }

  // ---- 3 H-cycles ----
  for (int hc = 0; hc < 3; ++hc){
    // ---- 6 L-cycles ----
    for (int lc = 0; lc < 6; ++lc){
      u64 accD[32];
#pragma unroll
      for (int i = 0; i < 32; ++i) accD[i] = 0ull;

      // h = gelu(z @ W_up + b_up) in 4 chunks of 256 cols; accD += h_chunk @ W_down_chunk
      for (int c = 0; c < 4; ++c){
        u64 accU[32];
#pragma unroll
        for (int i = 0; i < 32; ++i) accU[i] = 0ull;
        mm256(accU, sZ, W_up + c * 256, 1024, sW, tid, ty, tx);
        float4 bu0 = *(const float4*)(b_up + c * 256 + c0);
        float4 bu1 = *(const float4*)(b_up + c * 256 + 128 + c0);
#pragma unroll
        for (int i = 0; i < 8; ++i){
          float C[8]; UNPACK8(accU, i, C);
          float* hr = sH + (ty * 8 + i) * LDA;
          *(float4*)(hr + c0) = make_float4(
              gelu_exact(C[0]+bu0.x), gelu_exact(C[1]+bu0.y),
              gelu_exact(C[2]+bu0.z), gelu_exact(C[3]+bu0.w));
          *(float4*)(hr + 128 + c0) = make_float4(
              gelu_exact(C[4]+bu1.x), gelu_exact(C[5]+bu1.y),
              gelu_exact(C[6]+bu1.z), gelu_exact(C[7]+bu1.w));
        }
        // down-proj chunk: first internal __syncthreads of mm256 orders the sH writes
        mm256(accD, sH, W_down + c * 256 * 256, 256, sW, tid, ty, tx);
      }

      // ---- residual + LayerNorm, write back to sZ ----
      __syncthreads();
      float4 bd0 = *(const float4*)(b_down + c0);
      float4 bd1 = *(const float4*)(b_down + 128 + c0);
      float4 lw0 = *(const float4*)(ln_w + c0);
      float4 lw1 = *(const float4*)(ln_w + 128 + c0);
      float4 lb0 = *(const float4*)(ln_b + c0);
      float4 lb1 = *(const float4*)(ln_b + 128 + c0);
      float T[8][8], ps[8], pq[8];
#pragma unroll
      for (int i = 0; i < 8; ++i){
        float C[8]; UNPACK8(accD, i, C);
        const float* zr = sZ + (ty * 8 + i) * LDA;
        float4 z0 = *(const float4*)(zr + c0);
        float4 z1 = *(const float4*)(zr + 128 + c0);
        float v0 = z0.x + C[0] + bd0.x, v1 = z0.y + C[1] + bd0.y;
        float v2 = z0.z + C[2] + bd0.z, v3 = z0.w + C[3] + bd0.w;
        float v4 = z1.x + C[4] + bd1.x, v5 = z1.y + C[5] + bd1.y;
        float v6 = z1.z + C[6] + bd1.z, v7 = z1.w + C[7] + bd1.w;
        T[i][0]=v0; T[i][1]=v1; T[i][2]=v2; T[i][3]=v3;
        T[i][4]=v4; T[i][5]=v5; T[i][6]=v6; T[i][7]=v7;
        ps[i] = ((v0+v1)+(v2+v3)) + ((v4+v5)+(v6+v7));
        pq[i] = ((v0*v0+v1*v1)+(v2*v2+v3*v3)) + ((v4*v4+v5*v5)+(v6*v6+v7*v7));
      }
#pragma unroll
      for (int off = 16; off > 0; off >>= 1){
#pragma unroll
        for (int i = 0; i < 8; ++i){
          ps[i] += __shfl_xor_sync(0xffffffffu, ps[i], off);
          pq[i] += __shfl_xor_sync(0xffffffffu, pq[i], off);
        }
      }
#pragma unroll
      for (int i = 0; i < 8; ++i){
        float mu  = ps[i] * (1.0f / 256.0f);
        float var = pq[i] * (1.0f / 256.0f) - mu * mu;
        float rs  = rsqrtf(var + LN_EPS_F);
        float* zr = sZ + (ty * 8 + i) * LDA;
        *(float4*)(zr + c0) = make_float4(
            (T[i][0]-mu)*rs*lw0.x + lb0.x, (T[i][1]-mu)*rs*lw0.y + lb0.y,
            (T[i][2]-mu)*rs*lw0.z + lb0.z, (T[i][3]-mu)*rs*lw0.w + lb0.w);
        *(float4*)(zr + 128 + c0) = make_float4(
            (T[i][4]-mu)*rs*lw1.x + lb1.x, (T[i][5]-mu)*rs*lw1.y + lb1.y,
            (T[i][6]-mu)*rs*lw1.z + lb1.z, (T[i][7]-mu)*rs*lw1.w + lb1.w);
      }
      __syncthreads();
    }

    // ---- combine: h = gelu([z|y] @ W_comb + b_comb); y += h @ W_yt + b_yt ----
    {
      u64 acc[32];
#pragma unroll
      for (int i = 0; i < 32; ++i) acc[i] = 0ull;
      mm256(acc, sZ, W_comb,             256, sW, tid, ty, tx);
      mm256(acc, sY, W_comb + 256 * 256, 256, sW, tid, ty, tx);
      float4 bc0 = *(const float4*)(b_comb + c0);
      float4 bc1 = *(const float4*)(b_comb + 128 + c0);
#pragma unroll
      for (int i = 0; i < 8; ++i){
        float C[8]; UNPACK8(acc, i, C);
        float* hr = sH + (ty * 8 + i) * LDA;
        *(float4*)(hr + c0) = make_float4(
            gelu_exact(C[0]+bc0.x), gelu_exact(C[1]+bc0.y),
            gelu_exact(C[2]+bc0.z), gelu_exact(C[3]+bc0.w));
        *(float4*)(hr + 128 + c0) = make_float4(
            gelu_exact(C[4]+bc1.x), gelu_exact(C[5]+bc1.y),
            gelu_exact(C[6]+bc1.z), gelu_exact(C[7]+bc1.w));
      }
      u64 acc2[32];
#pragma unroll
      for (int i = 0; i < 32; ++i) acc2[i] = 0ull;
      mm256(acc2, sH, W_yt, 256, sW, tid, ty, tx);
      __syncthreads();
      float4 by0 = *(const float4*)(b_yt + c0);
      float4 by1 = *(const float4*)(b_yt + 128 + c0);
#pragma unroll
      for (int i = 0; i < 8; ++i){
        float C[8]; UNPACK8(acc2, i, C);
        float* yr = sY + (ty * 8 + i) * LDA;
        float4 y0 = *(const float4*)(yr + c0);
        float4 y1 = *(const float4*)(yr + 128 + c0);
        *(float4*)(yr + c0) = make_float4(
            y0.x + C[0] + by0.x, y0.y + C[1] + by0.y,
            y0.z + C[2] + by0.z, y0.w + C[3] + by0.w);
        *(float4*)(yr + 128 + c0) = make_float4(
            y1.x + C[4] + by1.x, y1.y + C[5] + by1.y,
            y1.z + C[6] + by1.z, y1.w + C[7] + by1.w);
      }
      __syncthreads();
    }
  }

  // ---- head: out = y @ W_head + b_head  (N=10) ----
  __syncthreads();
  for (int e = tid; e < MT * 10; e += NT){
    int m = e / 10;
    int n = e - m * 10;
    float s = b_head[n];
    const float* yr = sY + m * LDA;
    for (int k = 0; k < 256; ++k)
      s += yr[k] * W_head[k * 10 + n];
    out[(size_t)(r0 + m) * 10 + n] = s;
  }
}

extern "C" void kernel_launch(void* const* d_in, const int* in_sizes, int n_in,
                              void* d_out, int out_size)
{
  const float* x      = (const float*)d_in[0];
  const float* W_in   = (const float*)d_in[1];
  const float* b_in   = (const float*)d_in[2];
  const float* y_init = (const float*)d_in[3];
  const float* W_up   = (const float*)d_in[4];
  const float* b_up   = (const float*)d_in[5];
  const float* W_down = (const float*)d_in[6];
  const float* b_down = (const float*)d_in[7];
  const float* ln_w   = (const float*)d_in[8];
  const float* ln_b   = (const float*)d_in[9];
  const float* W_comb = (const float*)d_in[10];
  const float* b_comb = (const float*)d_in[11];
  const float* W_yt   = (const float*)d_in[12];
  const float* b_yt   = (const float*)d_in[13];
  const float* W_head = (const float*)d_in[14];
  const float* b_head = (const float*)d_in[15];
  float* out = (float*)d_out;

  const int B = in_sizes[0] / 256;           // rows
  const size_t smem = (size_t)(3 * MT * LDA + 2 * KS * 256) * sizeof(float); // 229376 B

  cudaFuncSetAttribute(trm_fused_kernel,
                       cudaFuncAttributeMaxDynamicSharedMemorySize, (int)smem);

  trm_fused_kernel<<<B / MT, NT, smem>>>(
      x, W_in, b_in, y_init, W_up, b_up, W_down, b_down,
      ln_w, ln_b, W_comb, b_comb, W_yt, b_yt, W_head, b_head, out);
}

// round 17
// speedup vs baseline: 1.6811x; 1.0007x over previous
#include <cuda_runtime.h>
#include <math.h>

// StandardTRM fused fp32 kernel, v4.
// Tile = 64 rows, 256 threads (8 warps), microtile 8 rows x 8 cols, but the
// 8 columns are now TWO 16-byte blocks: cols [tx*4..tx*4+3] and
// [128+tx*4..128+tx*4+3]. This makes every W shared-load and every epilogue
// store lane-contiguous (16B stride) -> ZERO bank conflicts. v1/v3 used one
// 32B block per lane (32B stride), a 2-way conflict on every LDS.128, which
// made the smem crossbar (144 cyc/k-step/SM) the binder over the fma pipe
// (128 cyc/k-step/SM). Also: weight slabs grow to 16 rows (16KB x2), halving
// barrier/cpwait count per matmul.

#define MT   64          // rows per CTA tile
#define LDA  256         // row stride (floats) for SMEM tiles
#define KS   16          // K rows per weight slab
#define NT   256         // threads per CTA
#define LN_EPS_F 1e-5f

typedef unsigned long long u64;

__device__ __forceinline__ u64 pk2(float x, float y){
  u64 r; asm("mov.b64 %0, {%1, %2};" : "=l"(r) : "f"(x), "f"(y)); return r;
}
__device__ __forceinline__ void upk2(u64 v, float& x, float& y){
  asm("mov.b64 {%0, %1}, %2;" : "=f"(x), "=f"(y) : "l"(v));
}
__device__ __forceinline__ void fma2(u64& c, u64 a, u64 b){
  asm("fma.rn.f32x2 %0, %1, %2, %0;" : "+l"(c) : "l"(a), "l"(b));
}
__device__ __forceinline__ void cp16(float* s, const float* g){
  unsigned a = (unsigned)__cvta_generic_to_shared(s);
  asm volatile("cp.async.cg.shared.global [%0], [%1], 16;" :: "r"(a), "l"(g));
}
__device__ __forceinline__ void cpcommit(){ asm volatile("cp.async.commit_group;" ::: "memory"); }
__device__ __forceinline__ void cpwait0(){ asm volatile("cp.async.wait_group 0;" ::: "memory"); }

__device__ __forceinline__ float gelu_exact(float v){
  return 0.5f * v * (1.0f + erff(v * 0.7071067811865475f));
}

// acc[i*4+0..1] = cols (c0, c0+1), (c0+2, c0+3); acc[i*4+2..3] = cols (+128).
#define UNPACK8(ACC, I, C) do {                         \
    upk2((ACC)[(I)*4+0], (C)[0], (C)[1]);               \
    upk2((ACC)[(I)*4+1], (C)[2], (C)[3]);               \
    upk2((ACC)[(I)*4+2], (C)[4], (C)[5]);               \
    upk2((ACC)[(I)*4+3], (C)[6], (C)[7]);               \
  } while(0)

// acc[64,256] (+)= sA[64, K=256] @ W[256 x 256cols], W row stride = ldw floats.
// Thread (ty,tx): rows ty*8..+7, cols {tx*4..+3} u {128+tx*4..+3}.
__device__ __forceinline__ void mm256(u64* __restrict__ acc,
                                      const float* __restrict__ sA,
                                      const float* __restrict__ gW, int ldw,
                                      float* __restrict__ sW,
                                      int tid, int ty, int tx)
{
  const int e  = tid * 16;     // this thread's 16-float chunk within a 16x256 slab
  const int er = e >> 8;
  const int ec = e & 255;
  // prefetch slab 0 into buffer 0
  {
    const float* src = gW + er * ldw + ec;
    cp16(sW + e,      src);
    cp16(sW + e + 4,  src + 4);
    cp16(sW + e + 8,  src + 8);
    cp16(sW + e + 12, src + 12);
    cpcommit();
  }
  const float* Abase = sA + ty * 8 * LDA;
  const int c0 = tx * 4;

  for (int s = 0; s < 16; ++s){
    cpwait0();
    __syncthreads();
    if (s < 15){
      float* dst = sW + ((s + 1) & 1) * (KS * 256);
      const float* src = gW + (s + 1) * KS * ldw + er * ldw + ec;
      cp16(dst + e,      src);
      cp16(dst + e + 4,  src + 4);
      cp16(dst + e + 8,  src + 8);
      cp16(dst + e + 12, src + 12);
      cpcommit();
    }
    const float* w = sW + (s & 1) * (KS * 256) + c0;
    const float* A = Abase + s * KS;
#pragma unroll
    for (int k4 = 0; k4 < KS; k4 += 4){
      float4 av[8];
#pragma unroll
      for (int i = 0; i < 8; ++i)
        av[i] = *(const float4*)(A + i * LDA + k4);    // warp-uniform broadcast
#pragma unroll
      for (int t = 0; t < 4; ++t){
        const float* wr = w + (k4 + t) * 256;
        ulonglong2 lo = *(const ulonglong2*)(wr);        // cols c0..c0+3  (16B stride, no conflicts)
        ulonglong2 hi = *(const ulonglong2*)(wr + 128);  // cols 128+c0..+3
#pragma unroll
        for (int i = 0; i < 8; ++i){
          float a = (t == 0) ? av[i].x : (t == 1) ? av[i].y : (t == 2) ? av[i].z : av[i].w;
          u64 a2 = pk2(a, a);
          fma2(acc[i*4+0], a2, lo.x);
          fma2(acc[i*4+1], a2, lo.y);
          fma2(acc[i*4+2], a2, hi.x);
          fma2(acc[i*4+3], a2, hi.y);
        }
      }
    }
  }
}

__global__ void __launch_bounds__(NT, 1)
trm_fused_kernel(const float* __restrict__ x,
                 const float* __restrict__ W_in,   const float* __restrict__ b_in,
                 const float* __restrict__ y_init,
                 const float* __restrict__ W_up,   const float* __restrict__ b_up,
                 const float* __restrict__ W_down, const float* __restrict__ b_down,
                 const float* __restrict__ ln_w,   const float* __restrict__ ln_b,
                 const float* __restrict__ W_comb, const float* __restrict__ b_comb,
                 const float* __restrict__ W_yt,   const float* __restrict__ b_yt,
                 const float* __restrict__ W_head, const float* __restrict__ b_head,
                 float* __restrict__ out)
{
  extern __shared__ float sm[];
  float* sZ = sm;                 // [64][256]
  float* sY = sZ + MT * LDA;      // [64][256]
  float* sH = sY + MT * LDA;      // [64][256]
  float* sW = sH + MT * LDA;      // 2 slabs of [16][256]

  const int tid = threadIdx.x;
  const int tx  = tid & 31;
  const int ty  = tid >> 5;       // warp id, owns rows 8*ty..8*ty+7
  const int c0  = tx * 4;         // first column block; second is c0+128
  const int r0  = blockIdx.x * MT;

  // ---- load x tile into sZ ----
  for (int e = tid * 4; e < MT * 256; e += NT * 4){
    int r = e >> 8, c = e & 255;
    *(float4*)(sZ + r * LDA + c) = *(const float4*)(x + (size_t)(r0 + r) * 256 + c);
  }
  __syncthreads();

  // ---- z = x @ W_in + b_in ; y = y_init ----
  {
    u64 acc[32];
#pragma unroll
    for (int i = 0; i < 32; ++i) acc[i] = 0ull;
    mm256(acc, sZ, W_in, 256, sW, tid, ty, tx);
    __syncthreads();                    // all reads of sZ (x data) done before overwrite
    float4 bi0 = *(const float4*)(b_in + c0);
    float4 bi1 = *(const float4*)(b_in + 128 + c0);
    float4 yv0 = *(const float4*)(y_init + c0);
    float4 yv1 = *(const float4*)(y_init + 128 + c0);
#pragma unroll
    for (int i = 0; i < 8; ++i){
      float C[8]; UNPACK8(acc, i, C);
      float* zr = sZ + (ty * 8 + i) * LDA;
      float* yr = sY + (ty * 8 + i) * LDA;
      *(float4*)(zr + c0)       = make_float4(C[0]+bi0.x, C[1]+bi0.y, C[2]+bi0.z, C[3]+bi0.w);
      *(float4*)(zr + 128 + c0) = make_float4(C[4]+bi1.x, C[5]+bi1.y, C[6]+bi1.z, C[7]+bi1.w);
      *(float4*)(yr + c0)       = yv0;
      *(float4*)(yr + 128 + c0) = yv1;
    }
    __syncthreads();
  }

  // ---- 3 H-cycles ----
  for (int hc = 0; hc < 3; ++hc){
    // ---- 6 L-cycles ----
    for (int lc = 0; lc < 6; ++lc){
      u64 accD[32];
#pragma unroll
      for (int i = 0; i < 32; ++i) accD[i] = 0ull;

      // h = gelu(z @ W_up + b_up) in 4 chunks of 256 cols; accD += h_chunk @ W_down_chunk
      for (int c = 0; c < 4; ++c){
        u64 accU[32];
#pragma unroll
        for (int i = 0; i < 32; ++i) accU[i] = 0ull;
        mm256(accU, sZ, W_up + c * 256, 1024, sW, tid, ty, tx);
        float4 bu0 = *(const float4*)(b_up + c * 256 + c0);
        float4 bu1 = *(const float4*)(b_up + c * 256 + 128 + c0);
#pragma unroll
        for (int i = 0; i < 8; ++i){
          float C[8]; UNPACK8(accU, i, C);
          float* hr = sH + (ty * 8 + i) * LDA;
          *(float4*)(hr + c0) = make_float4(
              gelu_exact(C[0]+bu0.x), gelu_exact(C[1]+bu0.y),
              gelu_exact(C[2]+bu0.z), gelu_exact(C[3]+bu0.w));
          *(float4*)(hr + 128 + c0) = make_float4(
              gelu_exact(C[4]+bu1.x), gelu_exact(C[5]+bu1.y),
              gelu_exact(C[6]+bu1.z), gelu_exact(C[7]+bu1.w));
        }
        // down-proj chunk: first internal __syncthreads of mm256 orders the sH writes
        mm256(accD, sH, W_down + c * 256 * 256, 256, sW, tid, ty, tx);
      }

      // ---- residual + LayerNorm, write back to sZ ----
      __syncthreads();
      float4 bd0 = *(const float4*)(b_down + c0);
      float4 bd1 = *(const float4*)(b_down + 128 + c0);
      float4 lw0 = *(const float4*)(ln_w + c0);
      float4 lw1 = *(const float4*)(ln_w + 128 + c0);
      float4 lb0 = *(const float4*)(ln_b + c0);
      float4 lb1 = *(const float4*)(ln_b + 128 + c0);
      float T[8][8], ps[8], pq[8];
#pragma unroll
      for (int i = 0; i < 8; ++i){
        float C[8]; UNPACK8(accD, i, C);
        const float* zr = sZ + (ty * 8 + i) * LDA;
        float4 z0 = *(const float4*)(zr + c0);
        float4 z1 = *(const float4*)(zr + 128 + c0);
        float v0 = z0.x + C[0] + bd0.x, v1 = z0.y + C[1] + bd0.y;
        float v2 = z0.z + C[2] + bd0.z, v3 = z0.w + C[3] + bd0.w;
        float v4 = z1.x + C[4] + bd1.x, v5 = z1.y + C[5] + bd1.y;
        float v6 = z1.z + C[6] + bd1.z, v7 = z1.w + C[7] + bd1.w;
        T[i][0]=v0; T[i][1]=v1; T[i][2]=v2; T[i][3]=v3;
        T[i][4]=v4; T[i][5]=v5; T[i][6]=v6; T[i][7]=v7;
        ps[i] = ((v0+v1)+(v2+v3)) + ((v4+v5)+(v6+v7));
        pq[i] = ((v0*v0+v1*v1)+(v2*v2+v3*v3)) + ((v4*v4+v5*v5)+(v6*v6+v7*v7));
      }
#pragma unroll
      for (int off = 16; off > 0; off >>= 1){
#pragma unroll
        for (int i = 0; i < 8; ++i){
          ps[i] += __shfl_xor_sync(0xffffffffu, ps[i], off);
          pq[i] += __shfl_xor_sync(0xffffffffu, pq[i], off);
        }
      }
#pragma unroll
      for (int i = 0; i < 8; ++i){
        float mu  = ps[i] * (1.0f / 256.0f);
        float var = pq[i] * (1.0f / 256.0f) - mu * mu;
        float rs  = rsqrtf(var + LN_EPS_F);
        float* zr = sZ + (ty * 8 + i) * LDA;
        *(float4*)(zr + c0) = make_float4(
            (T[i][0]-mu)*rs*lw0.x + lb0.x, (T[i][1]-mu)*rs*lw0.y + lb0.y,
            (T[i][2]-mu)*rs*lw0.z + lb0.z, (T[i][3]-mu)*rs*lw0.w + lb0.w);
        *(float4*)(zr + 128 + c0) = make_float4(
            (T[i][4]-mu)*rs*lw1.x + lb1.x, (T[i][5]-mu)*rs*lw1.y + lb1.y,
            (T[i][6]-mu)*rs*lw1.z + lb1.z, (T[i][7]-mu)*rs*lw1.w + lb1.w);
      }
      __syncthreads();
    }

    // ---- combine: h = gelu([z|y] @ W_comb + b_comb); y += h @ W_yt + b_yt ----
    {
      u64 acc[32];
#pragma unroll
      for (int i = 0; i < 32; ++i) acc[i] = 0ull;
      mm256(acc, sZ, W_comb,             256, sW, tid, ty, tx);
      mm256(acc, sY, W_comb + 256 * 256, 256, sW, tid, ty, tx);
      float4 bc0 = *(const float4*)(b_comb + c0);
      float4 bc1 = *(const float4*)(b_comb + 128 + c0);
#pragma unroll
      for (int i = 0; i < 8; ++i){
        float C[8]; UNPACK8(acc, i, C);
        float* hr = sH + (ty * 8 + i) * LDA;
        *(float4*)(hr + c0) = make_float4(
            gelu_exact(C[0]+bc0.x), gelu_exact(C[1]+bc0.y),
            gelu_exact(C[2]+bc0.z), gelu_exact(C[3]+bc0.w));
        *(float4*)(hr + 128 + c0) = make_float4(
            gelu_exact(C[4]+bc1.x), gelu_exact(C[5]+bc1.y),
            gelu_exact(C[6]+bc1.z), gelu_exact(C[7]+bc1.w));
      }
      u64 acc2[32];
#pragma unroll
      for (int i = 0; i < 32; ++i) acc2[i] = 0ull;
      mm256(acc2, sH, W_yt, 256, sW, tid, ty, tx);
      __syncthreads();
      float4 by0 = *(const float4*)(b_yt + c0);
      float4 by1 = *(const float4*)(b_yt + 128 + c0);
#pragma unroll
      for (int i = 0; i < 8; ++i){
        float C[8]; UNPACK8(acc2, i, C);
        float* yr = sY + (ty * 8 + i) * LDA;
        float4 y0 = *(const float4*)(yr + c0);
        float4 y1 = *(const float4*)(yr + 128 + c0);
        *(float4*)(yr + c0) = make_float4(
            y0.x + C[0] + by0.x, y0.y + C[1] + by0.y,
            y0.z + C[2] + by0.z, y0.w + C[3] + by0.w);
        *(float4*)(yr + 128 + c0) = make_float4(
            y1.x + C[4] + by1.x, y1.y + C[5] + by1.y,
            y1.z + C[6] + by1.z, y1.w + C[7] + by1.w);
      }
      __syncthreads();
    }
  }

  // ---- head: out = y @ W_head + b_head  (N=10) ----
  __syncthreads();
  for (int e = tid; e < MT * 10; e += NT){
    int m = e / 10;
    int n = e - m * 10;
    float s = b_head[n];
    const float* yr = sY + m * LDA;
    for (int k = 0; k < 256; ++k)
      s += yr[k] * W_head[k * 10 + n];
    out[(size_t)(r0 + m) * 10 + n] = s;
  }
}

extern "C" void kernel_launch(void* const* d_in, const int* in_sizes, int n_in,
                              void* d_out, int out_size)
{
  const float* x      = (const float*)d_in[0];
  const float* W_in   = (const float*)d_in[1];
  const float* b_in   = (const float*)d_in[2];
  const float* y_init = (const float*)d_in[3];
  const float* W_up   = (const float*)d_in[4];
  const float* b_up   = (const float*)d_in[5];
  const float* W_down = (const float*)d_in[6];
  const float* b_down = (const float*)d_in[7];
  const float* ln_w   = (const float*)d_in[8];
  const float* ln_b   = (const float*)d_in[9];
  const float* W_comb = (const float*)d_in[10];
  const float* b_comb = (const float*)d_in[11];
  const float* W_yt   = (const float*)d_in[12];
  const float* b_yt   = (const float*)d_in[13];
  const float* W_head = (const float*)d_in[14];
  const float* b_head = (const float*)d_in[15];
  float* out = (float*)d_out;

  const int B = in_sizes[0] / 256;           // rows
  const size_t smem = (size_t)(3 * MT * LDA + 2 * KS * 256) * sizeof(float); // 229376 B

  cudaFuncSetAttribute(trm_fused_kernel,
                       cudaFuncAttributeMaxDynamicSharedMemorySize, (int)smem);

  trm_fused_kernel<<<B / MT, NT, smem>>>(
      x, W_in, b_in, y_init, W_up, b_up, W_down, b_down,
      ln_w, ln_b, W_comb, b_comb, W_yt, b_yt, W_head, b_head, out);
}